// round 10
// baseline (speedup 1.0000x reference)
#include <cuda_runtime.h>

using u64 = unsigned long long;

// ---------------- problem constants -----------------------------------------
constexpr int Bn = 4;
constexpr int Nn = 8192;
constexpr int M2 = 8192;
constexpr int M3 = 4096;
constexpr int M4 = 2048;
constexpr int MM = 4096;

constexpr int NCX = 64;                 // cells per axis
constexpr int NCELLS = NCX * NCX;       // 4096
constexpr float GMIN = -48.f;
constexpr float CW   = 1.5f;
constexpr float INVCW = 0.66666669f;
constexpr float BIG  = 3.0e38f;
constexpr float MARG = 0.0625f;         // expansion margin >> fp error of d
constexpr unsigned FULL = 0xFFFFFFFFu;
constexpr int TOTAL_ELEMS = Bn * (M2 + M3 + M4 + MM + Nn);   // 106496

// padded group capacities per batch (elems padded to x4 per non-empty cell)
constexpr int CAPG2 = (M2 + 3 * NCELLS) / 4;    // 5120 groups
constexpr int CAPG3 = (M3 + 3 * NCELLS) / 4;    // 4096
constexpr int CAPG4 = (M4 + 3 * M4) / 4;        // 2048 (<=2048 non-empty cells)
constexpr int CAPGM = (MM + 3 * NCELLS) / 4;    // 4096

// ---------------- device scratch ---------------------------------------------
// interp record per 4-cand group: [x4|y4|z4|kk4|fv4] = 80 B; mask: 64 B
__device__ __align__(16) float g2buf[Bn * CAPG2 * 20];
__device__ __align__(16) float g3buf[Bn * CAPG3 * 20];
__device__ __align__(16) float g4buf[Bn * CAPG4 * 20];
__device__ __align__(16) float gmbuf[Bn * CAPGM * 16];
__device__ float qsx[Bn * Nn], qsy[Bn * Nn], qsz[Bn * Nn];
__device__ int   qsi[Bn * Nn];
__device__ int   gcnt[20 * NCELLS];      // arr = set(0..2)*4+b | 12+b | 16+b
__device__ int   gfil[20 * NCELLS];
__device__ int   goffs[20 * (NCELLS + 1)];
__device__ float g_v[96];

// ---------------- packed f32x2 helpers ----------------------------------------
__device__ __forceinline__ u64 ffma2u(u64 a, u64 b, u64 c) {
    u64 r;
    asm("fma.rn.f32x2 %0, %1, %2, %3;" : "=l"(r) : "l"(a), "l"(b), "l"(c));
    return r;
}
__device__ __forceinline__ u64 fadd2u(u64 a, u64 b) {
    u64 r;
    asm("add.rn.f32x2 %0, %1, %2;" : "=l"(r) : "l"(a), "l"(b));
    return r;
}
__device__ __forceinline__ float lo_(u64 v) { return __uint_as_float((unsigned)v); }
__device__ __forceinline__ float hi_(u64 v) { return __uint_as_float((unsigned)(v >> 32)); }
__device__ __forceinline__ u64 dup2(float x) {
    unsigned b = __float_as_uint(x);
    return ((u64)b << 32) | (u64)b;
}
__device__ __forceinline__ int cell1(float v) {
    int c = (int)((v - GMIN) * INVCW);
    return min(max(c, 0), NCX - 1);
}

// ---------------- element decode ------------------------------------------------
__device__ __forceinline__ void decode(int idx, int& arr, int& il, int& flat) {
    if (idx < 32768)      { arr = (idx >> 13);           il = idx & 8191; flat = idx; }
    else if (idx < 49152) { int j = idx - 32768; arr = 4  + (j >> 12); il = j & 4095; flat = j; }
    else if (idx < 57344) { int j = idx - 49152; arr = 8  + (j >> 11); il = j & 2047; flat = j; }
    else if (idx < 73728) { int j = idx - 57344; arr = 12 + (j >> 12); il = j & 4095; flat = j; }
    else                  { int j = idx - 73728; arr = 16 + (j >> 13); il = j & 8191; flat = j; }
}
__device__ __forceinline__ const float* src_of(int arr,
    const float* k2, const float* k3, const float* k4,
    const float* mp, const float* pt)
{
    if (arr < 4)  return k2;
    if (arr < 8)  return k3;
    if (arr < 12) return k4;
    if (arr < 16) return mp;
    return pt;
}

// ---------------- K0: sentinel-init record buffers + zero counters ---------------
__global__ void init_kernel() {
    int i = blockIdx.x * 256 + threadIdx.x;
    constexpr int A = Bn * CAPG2;                 // 20480 interp groups (g2)
    constexpr int B = A + Bn * CAPG3;             // 36864
    constexpr int C = B + Bn * CAPG4;             // 45056
    constexpr int D = C + Bn * CAPGM;             // 61440
    constexpr int E = D + 20 * NCELLS;            // 143360
    const float4 z4 = make_float4(0.f, 0.f, 0.f, 0.f);
    const float4 s4 = make_float4(1e30f, 1e30f, 1e30f, 1e30f);
    if (i < C) {
        float* gp;
        if (i < A)      gp = g2buf + (size_t)i * 20;
        else if (i < B) gp = g3buf + (size_t)(i - A) * 20;
        else            gp = g4buf + (size_t)(i - B) * 20;
        float4* p = reinterpret_cast<float4*>(gp);
        p[0] = z4; p[1] = z4; p[2] = z4; p[3] = s4; p[4] = z4;
    } else if (i < D) {
        float4* p = reinterpret_cast<float4*>(gmbuf + (size_t)(i - C) * 16);
        p[0] = z4; p[1] = z4; p[2] = z4; p[3] = s4;
    } else if (i < E) {
        gcnt[i - D] = 0; gfil[i - D] = 0;
    }
}

// ---------------- K1: histogram + g_v ---------------------------------------------
__global__ void hist_kernel(const float* __restrict__ k2, const float* __restrict__ k3,
    const float* __restrict__ k4, const float* __restrict__ mp,
    const float* __restrict__ pt,
    const float* __restrict__ w_fc, const float* __restrict__ w_cls)
{
    int idx = blockIdx.x * 256 + threadIdx.x;
    if (blockIdx.x == 0 && threadIdx.x < 96) {
        float acc = 0.f;
#pragma unroll
        for (int k = 0; k < 64; k++)
            acc = fmaf(w_cls[k], w_fc[k * 96 + threadIdx.x], acc);
        g_v[threadIdx.x] = acc;
    }
    if (idx >= TOTAL_ELEMS) return;
    int arr, il, flat;
    decode(idx, arr, il, flat);
    const float* src = src_of(arr, k2, k3, k4, mp, pt);
    int cell = cell1(src[flat * 3 + 1]) * NCX + cell1(src[flat * 3 + 0]);
    atomicAdd(&gcnt[arr * NCELLS + cell], 1);
}

// ---------------- K2: per-array exclusive prefix (padded counts) -------------------
__global__ void prefix_kernel() {
    int w = threadIdx.x >> 5, lane = threadIdx.x & 31;
    if (w >= 20) return;
    bool pad = (w < 16);
    int run = 0;
    for (int c0 = 0; c0 < NCELLS; c0 += 32) {
        int cell = c0 + lane;
        int c = gcnt[w * NCELLS + cell];
        if (pad) c = (c + 3) & ~3;
        int v = c;
#pragma unroll
        for (int o = 1; o < 32; o <<= 1) {
            int u = __shfl_up_sync(FULL, v, o);
            if (lane >= o) v += u;
        }
        goffs[w * (NCELLS + 1) + cell] = run + v - c;
        run += __shfl_sync(FULL, v, 31);
    }
    if (lane == 0) goffs[w * (NCELLS + 1) + NCELLS] = run;
}

// ---------------- K3: scatter into padded binned records ---------------------------
__global__ void scatter_kernel(const float* __restrict__ k2, const float* __restrict__ f2,
    const float* __restrict__ k3, const float* __restrict__ f3,
    const float* __restrict__ k4, const float* __restrict__ f4,
    const float* __restrict__ mp, const float* __restrict__ pt)
{
    int idx = blockIdx.x * 256 + threadIdx.x;
    if (idx >= TOTAL_ELEMS) return;
    int arr, il, flat;
    decode(idx, arr, il, flat);
    const float* src = src_of(arr, k2, k3, k4, mp, pt);
    float x = src[flat * 3 + 0];
    float y = src[flat * 3 + 1];
    float z = src[flat * 3 + 2];
    // same rounding order as jnp.sum(p*p, -1)
    float kk = __fadd_rn(__fadd_rn(__fmul_rn(x, x), __fmul_rn(y, y)), __fmul_rn(z, z));
    int cell = cell1(y) * NCX + cell1(x);
    int pos = goffs[arr * (NCELLS + 1) + cell] + atomicAdd(&gfil[arr * NCELLS + cell], 1);
    int b = arr & 3;

    if (arr < 12) {
        const float* feats; int voff; float* buf; int capg;
        if (arr < 4)      { feats = f2; voff = 0;  buf = g2buf; capg = CAPG2; }
        else if (arr < 8) { feats = f3; voff = 32; buf = g3buf; capg = CAPG3; }
        else              { feats = f4; voff = 64; buf = g4buf; capg = CAPG4; }
        float acc = 0.f;
        const float4* fp = reinterpret_cast<const float4*>(feats + (size_t)flat * 32);
#pragma unroll
        for (int j = 0; j < 8; j++) {
            float4 t = fp[j];
            acc = fmaf(t.x, g_v[voff + 4 * j + 0], acc);
            acc = fmaf(t.y, g_v[voff + 4 * j + 1], acc);
            acc = fmaf(t.z, g_v[voff + 4 * j + 2], acc);
            acc = fmaf(t.w, g_v[voff + 4 * j + 3], acc);
        }
        float* gp = buf + (size_t)(b * capg + (pos >> 2)) * 20;
        int sl = pos & 3;
        gp[sl] = x; gp[4 + sl] = y; gp[8 + sl] = z; gp[12 + sl] = kk; gp[16 + sl] = acc;
    } else if (arr < 16) {
        float* gp = gmbuf + (size_t)(b * CAPGM + (pos >> 2)) * 16;
        int sl = pos & 3;
        gp[sl] = x; gp[4 + sl] = y; gp[8 + sl] = z; gp[12 + sl] = kk;
    } else {
        int o = b * Nn + pos;
        qsx[o] = x; qsy[o] = y; qsz[o] = z;
        qsi[o] = b * Nn + il;                   // original global query index
    }
}

// ---------------- top-3 maintenance --------------------------------------------------
__device__ __forceinline__ void try_ins(float e, float fv,
                                        float& t0, float& t1, float& t2,
                                        float& f0, float& f1, float& f2) {
    if (e < t2) {
        if (e < t1) {
            t2 = t1; f2 = f1;
            if (e < t0) { t1 = t0; f1 = f0; t0 = e; f0 = fv; }
            else        { t1 = e;  f1 = fv; }
        } else { t2 = e; f2 = fv; }
    }
}

// one 4-cand group, interp: d = (qq+kk) - 2*dot (reference rounding order)
__device__ __forceinline__ void scan_group_i(const float* buf, int g,
    u64 c2x, u64 c2y, u64 c2z, u64 qq2,
    float& t0, float& t1, float& t2, float& f0, float& f1, float& f2)
{
    const char* p = reinterpret_cast<const char*>(buf) + (size_t)g * 80;
    ulonglong2 X = __ldg(reinterpret_cast<const ulonglong2*>(p));
    ulonglong2 Y = __ldg(reinterpret_cast<const ulonglong2*>(p + 16));
    ulonglong2 Z = __ldg(reinterpret_cast<const ulonglong2*>(p + 32));
    ulonglong2 W = __ldg(reinterpret_cast<const ulonglong2*>(p + 48));
    float4     F = __ldg(reinterpret_cast<const float4*>(p + 64));
    u64 dl = fadd2u(qq2, W.x);
    dl = ffma2u(c2x, X.x, dl); dl = ffma2u(c2y, Y.x, dl); dl = ffma2u(c2z, Z.x, dl);
    u64 dh = fadd2u(qq2, W.y);
    dh = ffma2u(c2x, X.y, dh); dh = ffma2u(c2y, Y.y, dh); dh = ffma2u(c2z, Z.y, dh);
    float d0 = lo_(dl), d1 = hi_(dl), d2 = lo_(dh), d3 = hi_(dh);
    float m = fminf(fminf(d0, d1), fminf(d2, d3));
    if (m < t2) {
        try_ins(d0, F.x, t0, t1, t2, f0, f1, f2);
        try_ins(d1, F.y, t0, t1, t2, f0, f1, f2);
        try_ins(d2, F.z, t0, t1, t2, f0, f1, f2);
        try_ins(d3, F.w, t0, t1, t2, f0, f1, f2);
    }
}

// ---------------- K4: scan (4-lane teams, one query each) ----------------------------
__global__ void __launch_bounds__(256)
scan_kernel(float* __restrict__ out) {
    const int team = (blockIdx.x * 256 + threadIdx.x) >> 2;
    const int sub  = threadIdx.x & 3;
    const int b    = team >> 13;
    const int pos  = team & 8191;
    const int qo   = b * Nn + pos;

    const float x = qsx[qo], y = qsy[qo], z = qsz[qo];
    const int   oi = qsi[qo];
    const float qq = __fadd_rn(__fadd_rn(__fmul_rn(x, x), __fmul_rn(y, y)),
                               __fmul_rn(z, z));
    const u64 c2x = dup2(-2.f * x), c2y = dup2(-2.f * y), c2z = dup2(-2.f * z);
    const u64 qq2 = dup2(qq);
    const int cqx = cell1(x), cqy = cell1(y);

    float pred = 0.f;
    const float* bufs[3] = { g2buf, g3buf, g4buf };
    const int    caps[3] = { CAPG2, CAPG3, CAPG4 };

#pragma unroll 1
    for (int s = 0; s < 3; s++) {
        const float* buf = bufs[s];
        const int* offs = goffs + (s * 4 + b) * (NCELLS + 1);
        const int gb0 = b * caps[s];
        float t0 = BIG, t1 = BIG, t2 = BIG, f0 = 0.f, f1 = 0.f, f2 = 0.f;

        int cxl = max(cqx - 1, 0), cxh = min(cqx + 1, NCX - 1);
        int cyl = max(cqy - 1, 0), cyh = min(cqy + 1, NCX - 1);
        for (int cy = cyl; cy <= cyh; cy++) {
            int lo = gb0 + (__ldg(offs + cy * NCX + cxl) >> 2);
            int hi = gb0 + (__ldg(offs + cy * NCX + cxh + 1) >> 2);
            for (int g = lo + sub; g < hi; g += 4)
                scan_group_i(buf, g, c2x, c2y, c2z, qq2, t0, t1, t2, f0, f1, f2);
        }

        while (true) {
            float t2b = fminf(t2, __shfl_xor_sync(FULL, t2, 1));
            t2b = fminf(t2b, __shfl_xor_sync(FULL, t2b, 2));
            float bnd = t2b + MARG;
            float gL = (cxl > 0)       ? (x - (GMIN + cxl * CW))       : BIG;
            float gR = (cxh < NCX - 1) ? ((GMIN + (cxh + 1) * CW) - x) : BIG;
            float gB = (cyl > 0)       ? (y - (GMIN + cyl * CW))       : BIG;
            float gT = (cyh < NCX - 1) ? ((GMIN + (cyh + 1) * CW) - y) : BIG;
            float gm = fminf(fminf(gL, gR), fminf(gB, gT));
            bool need = (gm < 1e30f) && (gm * gm < bnd);
            if (!__any_sync(FULL, need)) break;
            if (need) {
                if (gm == gL) {
                    cxl--;
                    for (int cy = cyl; cy <= cyh; cy++) {
                        int lo = gb0 + (__ldg(offs + cy * NCX + cxl) >> 2);
                        int hi = gb0 + (__ldg(offs + cy * NCX + cxl + 1) >> 2);
                        for (int g = lo + sub; g < hi; g += 4)
                            scan_group_i(buf, g, c2x, c2y, c2z, qq2, t0, t1, t2, f0, f1, f2);
                    }
                } else if (gm == gR) {
                    cxh++;
                    for (int cy = cyl; cy <= cyh; cy++) {
                        int lo = gb0 + (__ldg(offs + cy * NCX + cxh) >> 2);
                        int hi = gb0 + (__ldg(offs + cy * NCX + cxh + 1) >> 2);
                        for (int g = lo + sub; g < hi; g += 4)
                            scan_group_i(buf, g, c2x, c2y, c2z, qq2, t0, t1, t2, f0, f1, f2);
                    }
                } else if (gm == gB) {
                    cyl--;
                    int lo = gb0 + (__ldg(offs + cyl * NCX + cxl) >> 2);
                    int hi = gb0 + (__ldg(offs + cyl * NCX + cxh + 1) >> 2);
                    for (int g = lo + sub; g < hi; g += 4)
                        scan_group_i(buf, g, c2x, c2y, c2z, qq2, t0, t1, t2, f0, f1, f2);
                } else {
                    cyh++;
                    int lo = gb0 + (__ldg(offs + cyh * NCX + cxl) >> 2);
                    int hi = gb0 + (__ldg(offs + cyh * NCX + cxh + 1) >> 2);
                    for (int g = lo + sub; g < hi; g += 4)
                        scan_group_i(buf, g, c2x, c2y, c2z, qq2, t0, t1, t2, f0, f1, f2);
                }
            }
        }

        // butterfly merge across the 4 team lanes
#pragma unroll
        for (int o = 1; o <= 2; o <<= 1) {
            float rt0 = __shfl_xor_sync(FULL, t0, o), rf0 = __shfl_xor_sync(FULL, f0, o);
            float rt1 = __shfl_xor_sync(FULL, t1, o), rf1 = __shfl_xor_sync(FULL, f1, o);
            float rt2 = __shfl_xor_sync(FULL, t2, o), rf2 = __shfl_xor_sync(FULL, f2, o);
            try_ins(rt0, rf0, t0, t1, t2, f0, f1, f2);
            try_ins(rt1, rf1, t0, t1, t2, f0, f1, f2);
            try_ins(rt2, rf2, t0, t1, t2, f0, f1, f2);
        }
        float d0 = fmaxf(t0, 0.f), d1 = fmaxf(t1, 0.f), d2c = fmaxf(t2, 0.f);
        float r0 = 1.f / (d0 + 1e-8f);
        float r1 = 1.f / (d1 + 1e-8f);
        float r2 = 1.f / (d2c + 1e-8f);
        pred += fmaf(r0, f0, fmaf(r1, f1, r2 * f2)) / (r0 + r1 + r2);
    }

    // ---- mask: any(d2 < 0.25) over fixed 3x3 cells (gap >= 1.0m > 0.5m) ----
    int found = 0;
    {
        const int* offs = goffs + (12 + b) * (NCELLS + 1);
        const int gb0 = b * CAPGM;
        int cxl = max(cqx - 1, 0), cxh = min(cqx + 1, NCX - 1);
        int cyl = max(cqy - 1, 0), cyh = min(cqy + 1, NCX - 1);
        float tf = 0.3125f - qq;                    // margin fast path
        for (int cy = cyl; cy <= cyh; cy++) {
            int lo = gb0 + (__ldg(offs + cy * NCX + cxl) >> 2);
            int hi = gb0 + (__ldg(offs + cy * NCX + cxh + 1) >> 2);
            for (int g = lo + sub; g < hi; g += 4) {
                const char* p = reinterpret_cast<const char*>(gmbuf) + (size_t)g * 64;
                ulonglong2 X = __ldg(reinterpret_cast<const ulonglong2*>(p));
                ulonglong2 Y = __ldg(reinterpret_cast<const ulonglong2*>(p + 16));
                ulonglong2 Z = __ldg(reinterpret_cast<const ulonglong2*>(p + 32));
                ulonglong2 W = __ldg(reinterpret_cast<const ulonglong2*>(p + 48));
                u64 el = ffma2u(c2x, X.x, ffma2u(c2y, Y.x, ffma2u(c2z, Z.x, W.x)));
                u64 eh = ffma2u(c2x, X.y, ffma2u(c2y, Y.y, ffma2u(c2z, Z.y, W.y)));
                float m = fminf(fminf(lo_(el), hi_(el)), fminf(lo_(eh), hi_(eh)));
                if (m < tf) {                       // rare: exact recheck
                    float cx[4] = { lo_(X.x), hi_(X.x), lo_(X.y), hi_(X.y) };
                    float cy2[4] = { lo_(Y.x), hi_(Y.x), lo_(Y.y), hi_(Y.y) };
                    float cz[4] = { lo_(Z.x), hi_(Z.x), lo_(Z.y), hi_(Z.y) };
                    float cw[4] = { lo_(W.x), hi_(W.x), lo_(W.y), hi_(W.y) };
#pragma unroll
                    for (int c = 0; c < 4; c++) {
                        // bit-exact reference-mimic rounding
                        float dot = __fadd_rn(__fadd_rn(__fmul_rn(x, cx[c]),
                                                        __fmul_rn(y, cy2[c])),
                                              __fmul_rn(z, cz[c]));
                        float d = __fsub_rn(__fadd_rn(qq, cw[c]), __fadd_rn(dot, dot));
                        if (d < 0.25f) found = 1;
                    }
                }
            }
        }
        found |= __shfl_xor_sync(FULL, found, 1);
        found |= __shfl_xor_sync(FULL, found, 2);
    }

    if (sub == 0) {
        out[oi] = pred;                             // pred_hm (B,N,1)
        out[Bn * Nn + oi] = found ? 1.f : 0.f;      // gt_hm   (B,N)
    }
}

// ---------------- launch ---------------------------------------------------------------
extern "C" void kernel_launch(void* const* d_in, const int* in_sizes, int n_in,
                              void* d_out, int out_size) {
    (void)in_sizes; (void)n_in; (void)out_size;
    const float* pts    = (const float*)d_in[0];
    const float* known2 = (const float*)d_in[1];
    const float* feats2 = (const float*)d_in[2];
    const float* known3 = (const float*)d_in[3];
    const float* feats3 = (const float*)d_in[4];
    const float* known4 = (const float*)d_in[5];
    const float* feats4 = (const float*)d_in[6];
    const float* matchp = (const float*)d_in[7];
    const float* w_fc   = (const float*)d_in[8];
    const float* w_cls  = (const float*)d_in[9];
    float* out = (float*)d_out;

    constexpr int INIT_N = Bn * (CAPG2 + CAPG3 + CAPG4 + CAPGM) + 20 * NCELLS;
    const int eb = (TOTAL_ELEMS + 255) / 256;
    init_kernel<<<(INIT_N + 255) / 256, 256>>>();
    hist_kernel<<<eb, 256>>>(known2, known3, known4, matchp, pts, w_fc, w_cls);
    prefix_kernel<<<1, 640>>>();
    scatter_kernel<<<eb, 256>>>(known2, feats2, known3, feats3,
                                known4, feats4, matchp, pts);
    scan_kernel<<<(Bn * Nn * 4) / 256, 256>>>(out);   // 4 lanes per query
}